// round 14
// baseline (speedup 1.0000x reference)
#include <cuda_runtime.h>
#include <math.h>

#define Bq 2
#define Nn 8192
#define Cc 256
#define Kk 16
#define Dd 32
#define NR 4
#define RANGE (Nn / NR)
#define BN_INV 0.99999500003749969f
#define WVP 260   // wv row stride (floats): 16B-aligned, stride%32==4 -> conflict-free

// ---- scratch ----
__device__ float  g_q[Bq * Nn * Cc];
__device__ float  g_k[Bq * Nn * Cc];
__device__ float  g_v[Bq * Nn * Cc];
__device__ float2 g_kv2[Bq * Nn * Cc];     // {xk+pr, xv+pr}
__device__ float  g_tmp[Bq * Nn * Cc];     // fused output, [b][n][c]
__device__ int    g_idx[Bq * Nn * Kk];
__device__ float  g_pd[Bq * Nn * NR * Kk];
__device__ int    g_pi[Bq * Nn * NR * Kk];

__device__ __forceinline__ float2 two_sum(float a, float b) {
    float s  = __fadd_rn(a, b);
    float bp = __fsub_rn(s, a);
    float e  = __fadd_rn(__fsub_rn(a, __fsub_rn(s, bp)), __fsub_rn(b, bp));
    return make_float2(s, e);
}
__device__ __forceinline__ float2 two_prod(float a, float b) {
    float p = __fmul_rn(a, b);
    float e = __fmaf_rn(a, b, -p);
    return make_float2(p, e);
}

// ============================================================
// SUPER kernel: knn_part blocks first, then qkv blocks
// ============================================================
#define GM_BM 128
#define GM_BN 64
#define GM_BK 16
#define KNN_Q 256
#define KNN_TILE 256
#define CHUNK 64
#define KNN_NBLK ((Nn / KNN_Q) * NR * Bq)
#define QKV_NBLK ((Nn / GM_BM) * (Cc / GM_BN) * Bq)

__global__ __launch_bounds__(256, 3) void super_kernel(
    const float* __restrict__ feat, const float* __restrict__ xyz,
    const float* __restrict__ Wq, const float* __restrict__ bq,
    const float* __restrict__ Wk, const float* __restrict__ bk,
    const float* __restrict__ Wv, const float* __restrict__ bv)
{
    __shared__ __align__(16) union SM {
        struct { float As[GM_BK][GM_BM]; float Bs[GM_BK][GM_BN + 1]; } g;
        struct { float4 tile[KNN_TILE]; float tlo[KNN_TILE];
                 unsigned char buf[CHUNK][264]; } k;
    } sm;

    int bid = blockIdx.x;
    int tid = threadIdx.x;

    if (bid < KNN_NBLK) {
        int b   = bid / ((Nn / KNN_Q) * NR);
        int rem = bid % ((Nn / KNN_Q) * NR);
        int r   = rem >> 5;
        int qb  = rem & 31;
        int n   = qb * KNN_Q + tid;
        const float* xb = xyz + (size_t)b * Nn * 3;

        float qx = xb[n * 3 + 0], qy = xb[n * 3 + 1], qz = xb[n * 3 + 2];

        float sqn_hi, sqn_lo;
        {
            float2 q0 = two_prod(qx, qx), q1 = two_prod(qy, qy), q2 = two_prod(qz, qz);
            float2 s01 = two_sum(q0.x, q1.x);
            float2 s   = two_sum(s01.x, q2.x);
            sqn_hi = s.x;
            sqn_lo = s01.y + s.y + q0.y + q1.y + q2.y;
        }
        float qx2 = -2.0f * qx, qy2 = -2.0f * qy, qz2 = -2.0f * qz;

        float bd[Kk];
        int   bi[Kk];
#pragma unroll
        for (int i = 0; i < Kk; i++) { bd[i] = 3.4e38f; bi[i] = 0; }
        float cmax = 3.4e38f;

        int mbase = r * RANGE;
        for (int m0 = mbase; m0 < mbase + RANGE; m0 += KNN_TILE) {
            __syncthreads();
            {
                int j = tid;
                float x = xb[(m0 + j) * 3 + 0];
                float y = xb[(m0 + j) * 3 + 1];
                float z = xb[(m0 + j) * 3 + 2];
                float2 p0 = two_prod(x, x), p1 = two_prod(y, y), p2 = two_prod(z, z);
                float2 s01 = two_sum(p0.x, p1.x);
                float2 s   = two_sum(s01.x, p2.x);
                sm.k.tile[j] = make_float4(x, y, z, s.x);
                sm.k.tlo[j]  = s01.y + s.y + p0.y + p1.y + p2.y;
            }
            __syncthreads();

            for (int cb = 0; cb < KNN_TILE; cb += CHUNK) {
                float thrp = (cmax + 2e-5f) - sqn_hi;
                int cnt = 0;
#pragma unroll 4
                for (int j64 = 0; j64 < CHUNK; j64++) {
                    float4 cpt = sm.k.tile[cb + j64];
                    float t = fmaf(qx2, cpt.x, fmaf(qy2, cpt.y,
                              fmaf(qz2, cpt.z, cpt.w)));
                    bool hit = t < thrp;
                    sm.k.buf[cnt][tid] = (unsigned char)j64;
                    cnt += hit;
                }
                for (int t = 0; t < cnt; t++) {
                    int j = cb + (int)sm.k.buf[t][tid];
                    float4 cpt = sm.k.tile[j];
                    // FROZEN exact path (identical to R7-passing kernel)
                    float dot = __fmaf_rn(qz, cpt.z,
                                __fmaf_rn(qy, cpt.y,
                                __fmul_rn(qx, cpt.x)));
                    float m2dot = __fadd_rn(dot, dot);
                    float2 u1 = two_sum(sqn_hi, cpt.w);
                    float2 u2 = two_sum(u1.x, -m2dot);
                    float d2 = u2.x + (((u1.y + u2.y) + sqn_lo) + sm.k.tlo[j]);
                    if (d2 < bd[Kk - 1]) {
                        float v = d2;
                        int ii = m0 + j;
#pragma unroll
                        for (int i = 0; i < Kk; i++) {
                            if (v < bd[i]) {
                                float tv = bd[i]; int ti = bi[i];
                                bd[i] = v; bi[i] = ii;
                                v = tv; ii = ti;
                            }
                        }
                    }
                }
                cmax = bd[Kk - 1];
            }
        }

        size_t o = (((size_t)(b * Nn) + n) * NR + r) * Kk;
#pragma unroll
        for (int i = 0; i < Kk; i++) { g_pd[o + i] = bd[i]; g_pi[o + i] = bi[i]; }

    } else {
        int q   = bid - KNN_NBLK;
        int mat = q / QKV_NBLK;
        int rem = q % QKV_NBLK;
        int b   = rem >> 8;
        int t2  = rem & 255;
        int n0  = (t2 & 63) * GM_BM;
        int o0  = (t2 >> 6) * GM_BN;

        const float* W    = (mat == 0) ? Wq : (mat == 1) ? Wk : Wv;
        const float* bias = (mat == 0) ? bq : (mat == 1) ? bk : bv;
        float* out        = (mat == 0) ? g_q : (mat == 1) ? g_k : g_v;

        const float* fb = feat + (size_t)b * Cc * Nn;
        int ty = tid >> 4;
        int tx = tid & 15;

        float acc[8][4];
#pragma unroll
        for (int i = 0; i < 8; i++)
#pragma unroll
            for (int j = 0; j < 4; j++) acc[i][j] = 0.f;

        for (int c0 = 0; c0 < Cc; c0 += GM_BK) {
            {
                int r2 = tid >> 4;
                int col = (tid & 15) * 8;
                const float* src = fb + (size_t)(c0 + r2) * Nn + n0 + col;
                float4 v0 = *(const float4*)(src);
                float4 v1 = *(const float4*)(src + 4);
                *(float4*)&sm.g.As[r2][col]     = v0;
                *(float4*)&sm.g.As[r2][col + 4] = v1;
            }
            {
                int oo  = tid >> 2;
                int kc4 = (tid & 3) * 4;
                const float* src = W + (size_t)(o0 + oo) * Cc + c0 + kc4;
                float4 v = *(const float4*)src;
                sm.g.Bs[kc4 + 0][oo] = v.x;
                sm.g.Bs[kc4 + 1][oo] = v.y;
                sm.g.Bs[kc4 + 2][oo] = v.z;
                sm.g.Bs[kc4 + 3][oo] = v.w;
            }
            __syncthreads();
#pragma unroll
            for (int kc = 0; kc < GM_BK; kc++) {
                float a[8], bb[4];
#pragma unroll
                for (int i = 0; i < 8; i++) a[i] = sm.g.As[kc][ty * 8 + i];
#pragma unroll
                for (int j = 0; j < 4; j++) bb[j] = sm.g.Bs[kc][tx * 4 + j];
#pragma unroll
                for (int i = 0; i < 8; i++)
#pragma unroll
                    for (int j = 0; j < 4; j++)
                        acc[i][j] = fmaf(a[i], bb[j], acc[i][j]);
            }
            __syncthreads();
        }

        float* ob = out + (size_t)b * Nn * Cc;
        float4 bv4 = *(const float4*)(bias + o0 + tx * 4);
#pragma unroll
        for (int i = 0; i < 8; i++) {
            int n = n0 + ty * 8 + i;
            float4 r2;
            r2.x = fmaxf(acc[i][0] + bv4.x, 0.f);
            r2.y = fmaxf(acc[i][1] + bv4.y, 0.f);
            r2.z = fmaxf(acc[i][2] + bv4.z, 0.f);
            r2.w = fmaxf(acc[i][3] + bv4.w, 0.f);
            *(float4*)&ob[(size_t)n * Cc + o0 + tx * 4] = r2;
        }
    }
}

// ============================================================
// KNN merge (unchanged)
// ============================================================
#define KNN_TPB 128

__global__ __launch_bounds__(KNN_TPB) void knn_merge_kernel()
{
    int b = blockIdx.y;
    int n = blockIdx.x * KNN_TPB + threadIdx.x;

    float bd[Kk];
    int   bi[Kk];
#pragma unroll
    for (int i = 0; i < Kk; i++) { bd[i] = 3.4e38f; bi[i] = 0; }

    size_t base = ((size_t)(b * Nn) + n) * NR * Kk;
    for (int e = 0; e < NR * Kk; e++) {
        float v = g_pd[base + e];
        int  ii = g_pi[base + e];
        if (v < bd[Kk - 1]) {
#pragma unroll
            for (int i = 0; i < Kk; i++) {
                if (v < bd[i]) {
                    float tv = bd[i]; int ti = bi[i];
                    bd[i] = v; bi[i] = ii;
                    v = tv; ii = ti;
                }
            }
        }
    }

    int* op = g_idx + ((size_t)(b * Nn) + n) * Kk;
#pragma unroll
    for (int i = 0; i < Kk; i++) op[i] = bi[i];
}

// ============================================================
// prep: pr (verbatim expressions) then packed {xk+pr, xv+pr}
// ============================================================
__global__ __launch_bounds__(256) void prep_kernel(
    const float* __restrict__ xyz,
    const float* __restrict__ Wp1, const float* __restrict__ bp1,
    const float* __restrict__ g1,  const float* __restrict__ b1,
    const float* __restrict__ Wp2, const float* __restrict__ bp2)
{
    int bm = blockIdx.x;
    int c = threadIdx.x;
    const float* p = xyz + (size_t)bm * 3;
    float p0 = p[0], p1v = p[1], p2 = p[2];
    float t[3];
#pragma unroll
    for (int o = 0; o < 3; o++) {
        float u = Wp1[o * 3 + 0] * p0 + Wp1[o * 3 + 1] * p1v
                + Wp1[o * 3 + 2] * p2 + bp1[o];
        u = u * (g1[o] * BN_INV) + b1[o];
        t[o] = fmaxf(u, 0.f);
    }
    float wp20 = Wp2[c * 3 + 0], wp21 = Wp2[c * 3 + 1], wp22 = Wp2[c * 3 + 2];
    float pr = fmaxf(wp20 * t[0] + wp21 * t[1] + wp22 * t[2] + bp2[c], 0.f);
    size_t base = (size_t)bm * Cc + c;
    g_kv2[base] = make_float2(g_k[base] + pr, g_v[base] + pr);
}

// ============================================================
// fused attention: packed gather; SHUFFLE-FREE phase 3
// (thread = (d, kk-pair); Ww1 via L1; conflict-free wv stride)
// ============================================================
__global__ __launch_bounds__(256, 4) void fused_kernel(
    const float* __restrict__ g0,  const float* __restrict__ b0,
    const float* __restrict__ Ww1, const float* __restrict__ bw1,
    const float* __restrict__ g2,  const float* __restrict__ b2,
    const float* __restrict__ Ww2, const float* __restrict__ bw2)
{
    int bx = blockIdx.x;
    int b = bx >> 13;
    int n = bx & (Nn - 1);
    int tid = threadIdx.x;
    int c = tid;

    __shared__ __align__(16) float wv_s[Kk][WVP];   // padded rows
    __shared__ float w1_all[Kk][Dd + 1];
    __shared__ float w_s[Kk][Dd];
    __shared__ float w2t_s[Dd * Dd];
    __shared__ int   idx_s[Kk];

    for (int i = tid; i < Dd * Dd; i += 256)
        w2t_s[i] = Ww2[(i & 31) * Dd + (i >> 5)];
    if (tid < Kk) idx_s[tid] = g_idx[((size_t)(b * Nn) + n) * Kk + tid];

    float xqc = g_q[((size_t)(b * Nn) + n) * Cc + c];
    float s0c = g0[c] * BN_INV, h0c = b0[c];
    float bw2r = bw2[tid & 31];

    // phase-3 thread mapping: d3 = tid>>3 (0..31), kk pair = (k3, k3+8)
    int d3 = tid >> 3;
    int k3 = tid & 7;
    float bw1_d = bw1[d3];
    float s2_d  = g2[d3] * BN_INV;
    float h2_d  = b2[d3];

    __syncthreads();

    // phase 2: single packed gather per neighbor
    float vreg[Kk];
#pragma unroll 4
    for (int kk = 0; kk < Kk; kk++) {
        int m = idx_s[kk];
        float2 kv = g_kv2[((size_t)(b * Nn) + m) * Cc + c];
        wv_s[kk][c] = fmaxf((kv.x - xqc) * s0c + h0c, 0.f);
        vreg[kk] = kv.y;
    }
    __syncthreads();

    // phase 3: shuffle-free w1 GEMV — each thread: 2 outputs (d3,k3),(d3,k3+8)
    {
        float acc0 = 0.f, acc1 = 0.f;
        const float4* w1row = (const float4*)(Ww1 + (size_t)d3 * Cc);
        const float* r0 = &wv_s[k3][0];
        const float* r1 = &wv_s[k3 + 8][0];
#pragma unroll 8
        for (int c4 = 0; c4 < Cc / 4; c4++) {
            float4 w  = w1row[c4];
            float4 x0 = *(const float4*)(r0 + c4 * 4);
            float4 x1 = *(const float4*)(r1 + c4 * 4);
            acc0 = fmaf(w.x, x0.x, acc0); acc0 = fmaf(w.y, x0.y, acc0);
            acc0 = fmaf(w.z, x0.z, acc0); acc0 = fmaf(w.w, x0.w, acc0);
            acc1 = fmaf(w.x, x1.x, acc1); acc1 = fmaf(w.y, x1.y, acc1);
            acc1 = fmaf(w.z, x1.z, acc1); acc1 = fmaf(w.w, x1.w, acc1);
        }
        float u0 = (acc0 + bw1_d) * s2_d + h2_d;
        float u1 = (acc1 + bw1_d) * s2_d + h2_d;
        w1_all[k3][d3]     = fmaxf(u0, 0.f);
        w1_all[k3 + 8][d3] = fmaxf(u1, 0.f);
    }
    __syncthreads();

    // phase 4: w2 — 512 outputs, 2 per thread
#pragma unroll
    for (int r2 = 0; r2 < 2; r2++) {
        int oidx = tid + r2 * 256;
        int k = oidx >> 5, e = oidx & 31;
        float acc = bw2r;
#pragma unroll
        for (int dd = 0; dd < Dd; dd++)
            acc = fmaf(w2t_s[dd * Dd + e], w1_all[k][dd], acc);
        w_s[k][e] = fmaxf(acc, 0.f);
    }
    __syncthreads();

    // softmax over K
    if (tid < Dd) {
        float mx = -3.4e38f;
#pragma unroll
        for (int kk = 0; kk < Kk; kk++) mx = fmaxf(mx, w_s[kk][tid]);
        float sum = 0.f;
#pragma unroll
        for (int kk = 0; kk < Kk; kk++) {
            float e = expf(w_s[kk][tid] - mx);
            w_s[kk][tid] = e;
            sum += e;
        }
        float rs = 1.0f / sum;
#pragma unroll
        for (int kk = 0; kk < Kk; kk++) w_s[kk][tid] *= rs;
    }
    __syncthreads();

    // weighted neighbor reduction; coalesced store to [b][n][c]
    float acc = 0.f;
    int dd = c & 31;
#pragma unroll
    for (int kk = 0; kk < Kk; kk++)
        acc = fmaf(vreg[kk], w_s[kk][dd], acc);
    g_tmp[((size_t)(b * Nn) + n) * Cc + c] = acc;
}

// ============================================================
// transpose: g_tmp [b][n][c] -> out [b][c][n]
// ============================================================
__global__ __launch_bounds__(256) void transpose_kernel(float* __restrict__ out)
{
    __shared__ float tile[32][33];
    int b  = blockIdx.z;
    int n0 = blockIdx.x * 32;
    int c0 = blockIdx.y * 32;
    int tx = threadIdx.x & 31;
    int ty = threadIdx.x >> 5;

#pragma unroll
    for (int i = 0; i < 4; i++) {
        int nn = ty + i * 8;
        tile[nn][tx] = g_tmp[((size_t)b * Nn + n0 + nn) * Cc + c0 + tx];
    }
    __syncthreads();
#pragma unroll
    for (int i = 0; i < 4; i++) {
        int cc = ty + i * 8;
        out[((size_t)b * Cc + c0 + cc) * Nn + n0 + tx] = tile[tx][cc];
    }
}

// ============================================================
// launch: super(2), merge(3), prep(4), fused(5), transpose(6)
// ============================================================
extern "C" void kernel_launch(void* const* d_in, const int* in_sizes, int n_in,
                              void* d_out, int out_size)
{
    const float* xyz  = (const float*)d_in[0];
    const float* feat = (const float*)d_in[1];
    const float* Wq = (const float*)d_in[2];   const float* bqp = (const float*)d_in[3];
    const float* Wk = (const float*)d_in[4];   const float* bkp = (const float*)d_in[5];
    const float* Wv = (const float*)d_in[6];   const float* bvp = (const float*)d_in[7];
    const float* Wp1 = (const float*)d_in[8];  const float* bp1 = (const float*)d_in[9];
    const float* g1  = (const float*)d_in[10]; const float* b1  = (const float*)d_in[11];
    const float* Wp2 = (const float*)d_in[12]; const float* bp2 = (const float*)d_in[13];
    const float* g0  = (const float*)d_in[14]; const float* b0  = (const float*)d_in[15];
    const float* Ww1 = (const float*)d_in[16]; const float* bw1 = (const float*)d_in[17];
    const float* g2  = (const float*)d_in[18]; const float* b2  = (const float*)d_in[19];
    const float* Ww2 = (const float*)d_in[20]; const float* bw2 = (const float*)d_in[21];
    float* out = (float*)d_out;

    super_kernel<<<KNN_NBLK + 3 * QKV_NBLK, 256>>>(feat, xyz,
                                                   Wq, bqp, Wk, bkp, Wv, bvp);

    dim3 mgrid(Nn / KNN_TPB, Bq);
    knn_merge_kernel<<<mgrid, KNN_TPB>>>();

    prep_kernel<<<Bq * Nn, 256>>>(xyz, Wp1, bp1, g1, b1, Wp2, bp2);

    fused_kernel<<<Bq * Nn, 256>>>(g0, b0, Ww1, bw1, g2, b2, Ww2, bw2);

    dim3 tgrid(Nn / 32, Cc / 32, Bq);
    transpose_kernel<<<tgrid, 256>>>(out);
}

// round 15
// speedup vs baseline: 1.0854x; 1.0854x over previous
#include <cuda_runtime.h>
#include <math.h>

#define Bq 2
#define Nn 8192
#define Cc 256
#define Kk 16
#define Dd 32
#define NR 8
#define RANGE (Nn / NR)
#define BN_INV 0.99999500003749969f

// ---- scratch ----
__device__ float  g_q[Bq * Nn * Cc];
__device__ float  g_k[Bq * Nn * Cc];
__device__ float  g_v[Bq * Nn * Cc];
__device__ float2 g_kv2[Bq * Nn * Cc];     // {xk+pr, xv+pr}
__device__ float  g_tmp[Bq * Nn * Cc];     // fused output, [b][n][c]
__device__ int    g_idx[Bq * Nn * Kk];
__device__ float  g_pd[Bq * Nn * NR * Kk];
__device__ int    g_pi[Bq * Nn * NR * Kk];

__device__ __forceinline__ float2 two_sum(float a, float b) {
    float s  = __fadd_rn(a, b);
    float bp = __fsub_rn(s, a);
    float e  = __fadd_rn(__fsub_rn(a, __fsub_rn(s, bp)), __fsub_rn(b, bp));
    return make_float2(s, e);
}
__device__ __forceinline__ float2 two_prod(float a, float b) {
    float p = __fmul_rn(a, b);
    float e = __fmaf_rn(a, b, -p);
    return make_float2(p, e);
}

// ============================================================
// SUPER kernel: knn_part blocks first, then qkv blocks
// ============================================================
#define GM_BM 128
#define GM_BN 64
#define GM_BK 16
#define KNN_Q 256
#define KNN_TILE 256
#define CHUNK 64
#define KNN_NBLK ((Nn / KNN_Q) * NR * Bq)           // 512
#define QKV_NBLK ((Nn / GM_BM) * (Cc / GM_BN) * Bq) // 512 per matrix

__global__ __launch_bounds__(256, 3) void super_kernel(
    const float* __restrict__ feat, const float* __restrict__ xyz,
    const float* __restrict__ Wq, const float* __restrict__ bq,
    const float* __restrict__ Wk, const float* __restrict__ bk,
    const float* __restrict__ Wv, const float* __restrict__ bv)
{
    __shared__ __align__(16) union SM {
        struct { float As[GM_BK][GM_BM]; float Bs[GM_BK][GM_BN + 1]; } g;
        struct { float4 tile[KNN_TILE]; float tlo[KNN_TILE];
                 unsigned char buf[CHUNK][264]; } k;
    } sm;

    int bid = blockIdx.x;
    int tid = threadIdx.x;

    if (bid < KNN_NBLK) {
        int b   = bid / ((Nn / KNN_Q) * NR);
        int rem = bid % ((Nn / KNN_Q) * NR);
        int r   = rem >> 5;                 // Nn/KNN_Q == 32
        int qb  = rem & 31;
        int n   = qb * KNN_Q + tid;
        const float* xb = xyz + (size_t)b * Nn * 3;

        float qx = xb[n * 3 + 0], qy = xb[n * 3 + 1], qz = xb[n * 3 + 2];

        float sqn_hi, sqn_lo;
        {
            float2 q0 = two_prod(qx, qx), q1 = two_prod(qy, qy), q2 = two_prod(qz, qz);
            float2 s01 = two_sum(q0.x, q1.x);
            float2 s   = two_sum(s01.x, q2.x);
            sqn_hi = s.x;
            sqn_lo = s01.y + s.y + q0.y + q1.y + q2.y;
        }
        float qx2 = -2.0f * qx, qy2 = -2.0f * qy, qz2 = -2.0f * qz;

        float bd[Kk];
        int   bi[Kk];
#pragma unroll
        for (int i = 0; i < Kk; i++) { bd[i] = 3.4e38f; bi[i] = 0; }
        float cmax = 3.4e38f;

        int mbase = r * RANGE;
        for (int m0 = mbase; m0 < mbase + RANGE; m0 += KNN_TILE) {
            __syncthreads();
            {
                int j = tid;
                float x = xb[(m0 + j) * 3 + 0];
                float y = xb[(m0 + j) * 3 + 1];
                float z = xb[(m0 + j) * 3 + 2];
                float2 p0 = two_prod(x, x), p1 = two_prod(y, y), p2 = two_prod(z, z);
                float2 s01 = two_sum(p0.x, p1.x);
                float2 s   = two_sum(s01.x, p2.x);
                sm.k.tile[j] = make_float4(x, y, z, s.x);
                sm.k.tlo[j]  = s01.y + s.y + p0.y + p1.y + p2.y;
            }
            __syncthreads();

            for (int cb = 0; cb < KNN_TILE; cb += CHUNK) {
                float thrp = (cmax + 2e-5f) - sqn_hi;
                int cnt = 0;
#pragma unroll 4
                for (int j64 = 0; j64 < CHUNK; j64++) {
                    float4 cpt = sm.k.tile[cb + j64];
                    float t = fmaf(qx2, cpt.x, fmaf(qy2, cpt.y,
                              fmaf(qz2, cpt.z, cpt.w)));
                    bool hit = t < thrp;
                    sm.k.buf[cnt][tid] = (unsigned char)j64;
                    cnt += hit;
                }
                for (int t = 0; t < cnt; t++) {
                    int j = cb + (int)sm.k.buf[t][tid];
                    float4 cpt = sm.k.tile[j];
                    // FROZEN exact path (identical to R7-passing kernel)
                    float dot = __fmaf_rn(qz, cpt.z,
                                __fmaf_rn(qy, cpt.y,
                                __fmul_rn(qx, cpt.x)));
                    float m2dot = __fadd_rn(dot, dot);
                    float2 u1 = two_sum(sqn_hi, cpt.w);
                    float2 u2 = two_sum(u1.x, -m2dot);
                    float d2 = u2.x + (((u1.y + u2.y) + sqn_lo) + sm.k.tlo[j]);
                    if (d2 < bd[Kk - 1]) {
                        float v = d2;
                        int ii = m0 + j;
#pragma unroll
                        for (int i = 0; i < Kk; i++) {
                            if (v < bd[i]) {
                                float tv = bd[i]; int ti = bi[i];
                                bd[i] = v; bi[i] = ii;
                                v = tv; ii = ti;
                            }
                        }
                    }
                }
                cmax = bd[Kk - 1];
            }
        }

        size_t o = (((size_t)(b * Nn) + n) * NR + r) * Kk;
#pragma unroll
        for (int i = 0; i < Kk; i++) { g_pd[o + i] = bd[i]; g_pi[o + i] = bi[i]; }

    } else {
        int q   = bid - KNN_NBLK;
        int mat = q / QKV_NBLK;
        int rem = q % QKV_NBLK;
        int b   = rem >> 8;
        int t2  = rem & 255;
        int n0  = (t2 & 63) * GM_BM;
        int o0  = (t2 >> 6) * GM_BN;

        const float* W    = (mat == 0) ? Wq : (mat == 1) ? Wk : Wv;
        const float* bias = (mat == 0) ? bq : (mat == 1) ? bk : bv;
        float* out        = (mat == 0) ? g_q : (mat == 1) ? g_k : g_v;

        const float* fb = feat + (size_t)b * Cc * Nn;
        int ty = tid >> 4;
        int tx = tid & 15;

        float acc[8][4];
#pragma unroll
        for (int i = 0; i < 8; i++)
#pragma unroll
            for (int j = 0; j < 4; j++) acc[i][j] = 0.f;

        for (int c0 = 0; c0 < Cc; c0 += GM_BK) {
            {
                int r2 = tid >> 4;
                int col = (tid & 15) * 8;
                const float* src = fb + (size_t)(c0 + r2) * Nn + n0 + col;
                float4 v0 = *(const float4*)(src);
                float4 v1 = *(const float4*)(src + 4);
                *(float4*)&sm.g.As[r2][col]     = v0;
                *(float4*)&sm.g.As[r2][col + 4] = v1;
            }
            {
                int oo  = tid >> 2;
                int kc4 = (tid & 3) * 4;
                const float* src = W + (size_t)(o0 + oo) * Cc + c0 + kc4;
                float4 v = *(const float4*)src;
                sm.g.Bs[kc4 + 0][oo] = v.x;
                sm.g.Bs[kc4 + 1][oo] = v.y;
                sm.g.Bs[kc4 + 2][oo] = v.z;
                sm.g.Bs[kc4 + 3][oo] = v.w;
            }
            __syncthreads();
#pragma unroll
            for (int kc = 0; kc < GM_BK; kc++) {
                float a[8], bb[4];
#pragma unroll
                for (int i = 0; i < 8; i++) a[i] = sm.g.As[kc][ty * 8 + i];
#pragma unroll
                for (int j = 0; j < 4; j++) bb[j] = sm.g.Bs[kc][tx * 4 + j];
#pragma unroll
                for (int i = 0; i < 8; i++)
#pragma unroll
                    for (int j = 0; j < 4; j++)
                        acc[i][j] = fmaf(a[i], bb[j], acc[i][j]);
            }
            __syncthreads();
        }

        float* ob = out + (size_t)b * Nn * Cc;
        float4 bv4 = *(const float4*)(bias + o0 + tx * 4);
#pragma unroll
        for (int i = 0; i < 8; i++) {
            int n = n0 + ty * 8 + i;
            float4 r2;
            r2.x = fmaxf(acc[i][0] + bv4.x, 0.f);
            r2.y = fmaxf(acc[i][1] + bv4.y, 0.f);
            r2.z = fmaxf(acc[i][2] + bv4.z, 0.f);
            r2.w = fmaxf(acc[i][3] + bv4.w, 0.f);
            *(float4*)&ob[(size_t)n * Cc + o0 + tx * 4] = r2;
        }
    }
}

// ============================================================
// KNN merge — ranges ascending, strict-< insertion (identical order)
// ============================================================
#define KNN_TPB 128

__global__ __launch_bounds__(KNN_TPB) void knn_merge_kernel()
{
    int b = blockIdx.y;
    int n = blockIdx.x * KNN_TPB + threadIdx.x;

    float bd[Kk];
    int   bi[Kk];
#pragma unroll
    for (int i = 0; i < Kk; i++) { bd[i] = 3.4e38f; bi[i] = 0; }

    size_t base = ((size_t)(b * Nn) + n) * NR * Kk;
    for (int e = 0; e < NR * Kk; e++) {
        float v = g_pd[base + e];
        int  ii = g_pi[base + e];
        if (v < bd[Kk - 1]) {
#pragma unroll
            for (int i = 0; i < Kk; i++) {
                if (v < bd[i]) {
                    float tv = bd[i]; int ti = bi[i];
                    bd[i] = v; bi[i] = ii;
                    v = tv; ii = ti;
                }
            }
        }
    }

    int* op = g_idx + ((size_t)(b * Nn) + n) * Kk;
#pragma unroll
    for (int i = 0; i < Kk; i++) op[i] = bi[i];
}

// ============================================================
// prep: pr (verbatim expressions) then packed {xk+pr, xv+pr}
// ============================================================
__global__ __launch_bounds__(256) void prep_kernel(
    const float* __restrict__ xyz,
    const float* __restrict__ Wp1, const float* __restrict__ bp1,
    const float* __restrict__ g1,  const float* __restrict__ b1,
    const float* __restrict__ Wp2, const float* __restrict__ bp2)
{
    int bm = blockIdx.x;
    int c = threadIdx.x;
    const float* p = xyz + (size_t)bm * 3;
    float p0 = p[0], p1v = p[1], p2 = p[2];
    float t[3];
#pragma unroll
    for (int o = 0; o < 3; o++) {
        float u = Wp1[o * 3 + 0] * p0 + Wp1[o * 3 + 1] * p1v
                + Wp1[o * 3 + 2] * p2 + bp1[o];
        u = u * (g1[o] * BN_INV) + b1[o];
        t[o] = fmaxf(u, 0.f);
    }
    float wp20 = Wp2[c * 3 + 0], wp21 = Wp2[c * 3 + 1], wp22 = Wp2[c * 3 + 2];
    float pr = fmaxf(wp20 * t[0] + wp21 * t[1] + wp22 * t[2] + bp2[c], 0.f);
    size_t base = (size_t)bm * Cc + c;
    g_kv2[base] = make_float2(g_k[base] + pr, g_v[base] + pr);
}

// ============================================================
// fused attention: packed gather; R13-proven butterfly phase 3;
// phase 4 with w2t register reuse (2 k per warp); coalesced out
// ============================================================
__global__ __launch_bounds__(256, 4) void fused_kernel(
    const float* __restrict__ g0,  const float* __restrict__ b0,
    const float* __restrict__ Ww1, const float* __restrict__ bw1,
    const float* __restrict__ g2,  const float* __restrict__ b2,
    const float* __restrict__ Ww2, const float* __restrict__ bw2)
{
    int bx = blockIdx.x;
    int b = bx >> 13;
    int n = bx & (Nn - 1);
    int tid = threadIdx.x;
    int c = tid;
    int warp = tid >> 5;
    int lane = tid & 31;

    __shared__ __align__(16) float wv_s[Kk][Cc];
    __shared__ float w1_all[Kk][Dd];
    __shared__ float w_s[Kk][Dd];
    __shared__ float w2t_s[Dd * Dd];
    __shared__ int   idx_s[Kk];

    for (int i = tid; i < Dd * Dd; i += 256)
        w2t_s[i] = Ww2[(i & 31) * Dd + (i >> 5)];
    if (tid < Kk) idx_s[tid] = g_idx[((size_t)(b * Nn) + n) * Kk + tid];

    float xqc = g_q[((size_t)(b * Nn) + n) * Cc + c];
    float s0c = g0[c] * BN_INV, h0c = b0[c];
    float bw2r = bw2[lane];

    // R13-proven phase-3 weights: warp handles d = 4*warp..4*warp+3
    float w4[4][8];
#pragma unroll
    for (int i = 0; i < 4; i++) {
        const float* wr = Ww1 + (size_t)(4 * warp + i) * Cc + 4 * lane;
        float4 t0 = *(const float4*)(wr);
        float4 t1 = *(const float4*)(wr + 128);
        w4[i][0] = t0.x; w4[i][1] = t0.y; w4[i][2] = t0.z; w4[i][3] = t0.w;
        w4[i][4] = t1.x; w4[i][5] = t1.y; w4[i][6] = t1.z; w4[i][7] = t1.w;
    }
    int d_l = 4 * warp + (lane & 3);
    float bw1_l = bw1[d_l];
    float s2_l  = g2[d_l] * BN_INV;
    float h2_l  = b2[d_l];

    __syncthreads();

    // phase 2: single packed gather per neighbor
    float vreg[Kk];
#pragma unroll 4
    for (int kk = 0; kk < Kk; kk++) {
        int m = idx_s[kk];
        float2 kv = g_kv2[((size_t)(b * Nn) + m) * Cc + c];
        wv_s[kk][c] = fmaxf((kv.x - xqc) * s0c + h0c, 0.f);
        vreg[kk] = kv.y;
    }
    __syncthreads();

    // phase 3: w1 GEMV, 4 d per warp over full c (R13-proven butterfly)
#pragma unroll 4
    for (int kk = 0; kk < Kk; kk++) {
        const float4* wrow = (const float4*)(&wv_s[kk][0]);
        float4 v0 = wrow[lane];
        float4 v1 = wrow[lane + 32];
        float a0 = 0.f, a1 = 0.f, a2 = 0.f, a3 = 0.f;
        a0 = fmaf(w4[0][0], v0.x, a0); a0 = fmaf(w4[0][1], v0.y, a0);
        a0 = fmaf(w4[0][2], v0.z, a0); a0 = fmaf(w4[0][3], v0.w, a0);
        a0 = fmaf(w4[0][4], v1.x, a0); a0 = fmaf(w4[0][5], v1.y, a0);
        a0 = fmaf(w4[0][6], v1.z, a0); a0 = fmaf(w4[0][7], v1.w, a0);
        a1 = fmaf(w4[1][0], v0.x, a1); a1 = fmaf(w4[1][1], v0.y, a1);
        a1 = fmaf(w4[1][2], v0.z, a1); a1 = fmaf(w4[1][3], v0.w, a1);
        a1 = fmaf(w4[1][4], v1.x, a1); a1 = fmaf(w4[1][5], v1.y, a1);
        a1 = fmaf(w4[1][6], v1.z, a1); a1 = fmaf(w4[1][7], v1.w, a1);
        a2 = fmaf(w4[2][0], v0.x, a2); a2 = fmaf(w4[2][1], v0.y, a2);
        a2 = fmaf(w4[2][2], v0.z, a2); a2 = fmaf(w4[2][3], v0.w, a2);
        a2 = fmaf(w4[2][4], v1.x, a2); a2 = fmaf(w4[2][5], v1.y, a2);
        a2 = fmaf(w4[2][6], v1.z, a2); a2 = fmaf(w4[2][7], v1.w, a2);
        a3 = fmaf(w4[3][0], v0.x, a3); a3 = fmaf(w4[3][1], v0.y, a3);
        a3 = fmaf(w4[3][2], v0.z, a3); a3 = fmaf(w4[3][3], v0.w, a3);
        a3 = fmaf(w4[3][4], v1.x, a3); a3 = fmaf(w4[3][5], v1.y, a3);
        a3 = fmaf(w4[3][6], v1.z, a3); a3 = fmaf(w4[3][7], v1.w, a3);
#pragma unroll
        for (int off = 16; off > 0; off >>= 1) {
            a0 += __shfl_xor_sync(0xffffffffu, a0, off);
            a1 += __shfl_xor_sync(0xffffffffu, a1, off);
            a2 += __shfl_xor_sync(0xffffffffu, a2, off);
            a3 += __shfl_xor_sync(0xffffffffu, a3, off);
        }
        if (lane < 4) {
            float t01 = (lane & 1) ? a1 : a0;
            float t23 = (lane & 1) ? a3 : a2;
            float part = (lane & 2) ? t23 : t01;
            float u = (part + bw1_l) * s2_l + h2_l;
            w1_all[kk][4 * warp + lane] = fmaxf(u, 0.f);
        }
    }
    __syncthreads();

    // phase 4: w2 — warp computes k in {2*warp, 2*warp+1}, e = lane;
    // w2t value loaded ONCE per dd feeds both k-chains.
    // per-output dd-ascending FMA order identical to previous rounds.
    {
        int k0 = 2 * warp, k1 = k0 + 1;
        float acc0 = bw2r, acc1 = bw2r;
#pragma unroll
        for (int dd = 0; dd < Dd; dd++) {
            float wv2 = w2t_s[dd * Dd + lane];
            acc0 = fmaf(wv2, w1_all[k0][dd], acc0);
            acc1 = fmaf(wv2, w1_all[k1][dd], acc1);
        }
        w_s[k0][lane] = fmaxf(acc0, 0.f);
        w_s[k1][lane] = fmaxf(acc1, 0.f);
    }
    __syncthreads();

    // softmax over K
    if (tid < Dd) {
        float mx = -3.4e38f;
#pragma unroll
        for (int kk = 0; kk < Kk; kk++) mx = fmaxf(mx, w_s[kk][tid]);
        float sum = 0.f;
#pragma unroll
        for (int kk = 0; kk < Kk; kk++) {
            float e = expf(w_s[kk][tid] - mx);
            w_s[kk][tid] = e;
            sum += e;
        }
        float rs = 1.0f / sum;
#pragma unroll
        for (int kk = 0; kk < Kk; kk++) w_s[kk][tid] *= rs;
    }
    __syncthreads();

    // weighted neighbor reduction; coalesced store to [b][n][c]
    float acc = 0.f;
    int dd = c & 31;
#pragma unroll
    for (int kk = 0; kk < Kk; kk++)
        acc = fmaf(vreg[kk], w_s[kk][dd], acc);
    g_tmp[((size_t)(b * Nn) + n) * Cc + c] = acc;
}

// ============================================================
// transpose: g_tmp [b][n][c] -> out [b][c][n]
// ============================================================
__global__ __launch_bounds__(256) void transpose_kernel(float* __restrict__ out)
{
    __shared__ float tile[32][33];
    int b  = blockIdx.z;
    int n0 = blockIdx.x * 32;
    int c0 = blockIdx.y * 32;
    int tx = threadIdx.x & 31;
    int ty = threadIdx.x >> 5;

#pragma unroll
    for (int i = 0; i < 4; i++) {
        int nn = ty + i * 8;
        tile[nn][tx] = g_tmp[((size_t)b * Nn + n0 + nn) * Cc + c0 + tx];
    }
    __syncthreads();
#pragma unroll
    for (int i = 0; i < 4; i++) {
        int cc = ty + i * 8;
        out[((size_t)b * Cc + c0 + cc) * Nn + n0 + tx] = tile[tx][cc];
    }
}

// ============================================================
// launch: super(2), merge(3), prep(4), fused(5), transpose(6)
// ============================================================
extern "C" void kernel_launch(void* const* d_in, const int* in_sizes, int n_in,
                              void* d_out, int out_size)
{
    const float* xyz  = (const float*)d_in[0];
    const float* feat = (const float*)d_in[1];
    const float* Wq = (const float*)d_in[2];   const float* bqp = (const float*)d_in[3];
    const float* Wk = (const float*)d_in[4];   const float* bkp = (const float*)d_in[5];
    const float* Wv = (const float*)d_in[6];   const float* bvp = (const float*)d_in[7];
    const float* Wp1 = (const float*)d_in[8];  const float* bp1 = (const float*)d_in[9];
    const float* g1  = (const float*)d_in[10]; const float* b1  = (const float*)d_in[11];
    const float* Wp2 = (const float*)d_in[12]; const float* bp2 = (const float*)d_in[13];
    const float* g0  = (const float*)d_in[14]; const float* b0  = (const float*)d_in[15];
    const float* Ww1 = (const float*)d_in[16]; const float* bw1 = (const float*)d_in[17];
    const float* g2  = (const float*)d_in[18]; const float* b2  = (const float*)d_in[19];
    const float* Ww2 = (const float*)d_in[20]; const float* bw2 = (const float*)d_in[21];
    float* out = (float*)d_out;

    super_kernel<<<KNN_NBLK + 3 * QKV_NBLK, 256>>>(feat, xyz,
                                                   Wq, bqp, Wk, bkp, Wv, bvp);

    dim3 mgrid(Nn / KNN_TPB, Bq);
    knn_merge_kernel<<<mgrid, KNN_TPB>>>();

    prep_kernel<<<Bq * Nn, 256>>>(xyz, Wp1, bp1, g1, b1, Wp2, bp2);

    fused_kernel<<<Bq * Nn, 256>>>(g0, b0, Ww1, bw1, g2, b2, Ww2, bw2);

    dim3 tgrid(Nn / 32, Cc / 32, Bq);
    transpose_kernel<<<tgrid, 256>>>(out);
}

// round 16
// speedup vs baseline: 1.1937x; 1.0999x over previous
#include <cuda_runtime.h>
#include <cuda_fp16.h>
#include <math.h>

#define Bq 2
#define Nn 8192
#define Cc 256
#define Kk 16
#define Dd 32
#define NR 4
#define RANGE (Nn / NR)
#define BN_INV 0.99999500003749969f

// ---- scratch ----
__device__ float  g_q[Bq * Nn * Cc];
__device__ float  g_k[Bq * Nn * Cc];
__device__ float  g_v[Bq * Nn * Cc];
__device__ float2 g_kv2[Bq * Nn * Cc];     // {xk+pr, xv+pr}
__device__ float  g_tmp[Bq * Nn * Cc];     // fused output, [b][n][c]
__device__ int    g_idx[Bq * Nn * Kk];
__device__ float  g_pd[Bq * Nn * NR * Kk];
__device__ int    g_pi[Bq * Nn * NR * Kk];

__device__ __forceinline__ float2 two_sum(float a, float b) {
    float s  = __fadd_rn(a, b);
    float bp = __fsub_rn(s, a);
    float e  = __fadd_rn(__fsub_rn(a, __fsub_rn(s, bp)), __fsub_rn(b, bp));
    return make_float2(s, e);
}
__device__ __forceinline__ float2 two_prod(float a, float b) {
    float p = __fmul_rn(a, b);
    float e = __fmaf_rn(a, b, -p);
    return make_float2(p, e);
}

// ============================================================
// SUPER kernel: knn_part blocks first, then qkv blocks
// ============================================================
#define GM_BM 128
#define GM_BN 64
#define GM_BK 16
#define KNN_Q 256
#define KNN_TILE 256
#define CHUNK 64
#define KNN_NBLK ((Nn / KNN_Q) * NR * Bq)           // 256
#define QKV_NBLK ((Nn / GM_BM) * (Cc / GM_BN) * Bq) // 512 per matrix

__global__ __launch_bounds__(256, 3) void super_kernel(
    const float* __restrict__ feat, const float* __restrict__ xyz,
    const float* __restrict__ Wq, const float* __restrict__ bq,
    const float* __restrict__ Wk, const float* __restrict__ bk,
    const float* __restrict__ Wv, const float* __restrict__ bv)
{
    __shared__ __align__(16) union SM {
        struct { float As[GM_BK][GM_BM]; float Bs[GM_BK][GM_BN + 1]; } g;
        struct { float4 tile[KNN_TILE]; float tlo[KNN_TILE];
                 unsigned char buf[CHUNK][264]; } k;
    } sm;

    int bid = blockIdx.x;
    int tid = threadIdx.x;

    if (bid < KNN_NBLK) {
        int b   = bid / ((Nn / KNN_Q) * NR);
        int rem = bid % ((Nn / KNN_Q) * NR);
        int r   = rem >> 5;                 // Nn/KNN_Q == 32
        int qb  = rem & 31;
        int n   = qb * KNN_Q + tid;
        const float* xb = xyz + (size_t)b * Nn * 3;

        float qx = xb[n * 3 + 0], qy = xb[n * 3 + 1], qz = xb[n * 3 + 2];

        float sqn_hi, sqn_lo;
        {
            float2 q0 = two_prod(qx, qx), q1 = two_prod(qy, qy), q2 = two_prod(qz, qz);
            float2 s01 = two_sum(q0.x, q1.x);
            float2 s   = two_sum(s01.x, q2.x);
            sqn_hi = s.x;
            sqn_lo = s01.y + s.y + q0.y + q1.y + q2.y;
        }
        float qx2 = -2.0f * qx, qy2 = -2.0f * qy, qz2 = -2.0f * qz;

        float bd[Kk];
        int   bi[Kk];
#pragma unroll
        for (int i = 0; i < Kk; i++) { bd[i] = 3.4e38f; bi[i] = 0; }
        float cmax = 3.4e38f;

        int mbase = r * RANGE;
        for (int m0 = mbase; m0 < mbase + RANGE; m0 += KNN_TILE) {
            __syncthreads();
            {
                int j = tid;
                float x = xb[(m0 + j) * 3 + 0];
                float y = xb[(m0 + j) * 3 + 1];
                float z = xb[(m0 + j) * 3 + 2];
                float2 p0 = two_prod(x, x), p1 = two_prod(y, y), p2 = two_prod(z, z);
                float2 s01 = two_sum(p0.x, p1.x);
                float2 s   = two_sum(s01.x, p2.x);
                sm.k.tile[j] = make_float4(x, y, z, s.x);
                sm.k.tlo[j]  = s01.y + s.y + p0.y + p1.y + p2.y;
            }
            __syncthreads();

            for (int cb = 0; cb < KNN_TILE; cb += CHUNK) {
                float thrp = (cmax + 2e-5f) - sqn_hi;
                int cnt = 0;
#pragma unroll 4
                for (int j64 = 0; j64 < CHUNK; j64++) {
                    float4 cpt = sm.k.tile[cb + j64];
                    float t = fmaf(qx2, cpt.x, fmaf(qy2, cpt.y,
                              fmaf(qz2, cpt.z, cpt.w)));
                    bool hit = t < thrp;
                    sm.k.buf[cnt][tid] = (unsigned char)j64;
                    cnt += hit;
                }
                for (int t = 0; t < cnt; t++) {
                    int j = cb + (int)sm.k.buf[t][tid];
                    float4 cpt = sm.k.tile[j];
                    // FROZEN exact path (identical to R7-passing kernel)
                    float dot = __fmaf_rn(qz, cpt.z,
                                __fmaf_rn(qy, cpt.y,
                                __fmul_rn(qx, cpt.x)));
                    float m2dot = __fadd_rn(dot, dot);
                    float2 u1 = two_sum(sqn_hi, cpt.w);
                    float2 u2 = two_sum(u1.x, -m2dot);
                    float d2 = u2.x + (((u1.y + u2.y) + sqn_lo) + sm.k.tlo[j]);
                    if (d2 < bd[Kk - 1]) {
                        float v = d2;
                        int ii = m0 + j;
#pragma unroll
                        for (int i = 0; i < Kk; i++) {
                            if (v < bd[i]) {
                                float tv = bd[i]; int ti = bi[i];
                                bd[i] = v; bi[i] = ii;
                                v = tv; ii = ti;
                            }
                        }
                    }
                }
                cmax = bd[Kk - 1];
            }
        }

        size_t o = (((size_t)(b * Nn) + n) * NR + r) * Kk;
#pragma unroll
        for (int i = 0; i < Kk; i++) { g_pd[o + i] = bd[i]; g_pi[o + i] = bi[i]; }

    } else {
        int q   = bid - KNN_NBLK;
        int mat = q / QKV_NBLK;
        int rem = q % QKV_NBLK;
        int b   = rem >> 8;
        int t2  = rem & 255;
        int n0  = (t2 & 63) * GM_BM;
        int o0  = (t2 >> 6) * GM_BN;

        const float* W    = (mat == 0) ? Wq : (mat == 1) ? Wk : Wv;
        const float* bias = (mat == 0) ? bq : (mat == 1) ? bk : bv;
        float* out        = (mat == 0) ? g_q : (mat == 1) ? g_k : g_v;

        const float* fb = feat + (size_t)b * Cc * Nn;
        int ty = tid >> 4;
        int tx = tid & 15;

        float acc[8][4];
#pragma unroll
        for (int i = 0; i < 8; i++)
#pragma unroll
            for (int j = 0; j < 4; j++) acc[i][j] = 0.f;

        for (int c0 = 0; c0 < Cc; c0 += GM_BK) {
            {
                int r2 = tid >> 4;
                int col = (tid & 15) * 8;
                const float* src = fb + (size_t)(c0 + r2) * Nn + n0 + col;
                float4 v0 = *(const float4*)(src);
                float4 v1 = *(const float4*)(src + 4);
                *(float4*)&sm.g.As[r2][col]     = v0;
                *(float4*)&sm.g.As[r2][col + 4] = v1;
            }
            {
                int oo  = tid >> 2;
                int kc4 = (tid & 3) * 4;
                const float* src = W + (size_t)(o0 + oo) * Cc + c0 + kc4;
                float4 v = *(const float4*)src;
                sm.g.Bs[kc4 + 0][oo] = v.x;
                sm.g.Bs[kc4 + 1][oo] = v.y;
                sm.g.Bs[kc4 + 2][oo] = v.z;
                sm.g.Bs[kc4 + 3][oo] = v.w;
            }
            __syncthreads();
#pragma unroll
            for (int kc = 0; kc < GM_BK; kc++) {
                float a[8], bb[4];
#pragma unroll
                for (int i = 0; i < 8; i++) a[i] = sm.g.As[kc][ty * 8 + i];
#pragma unroll
                for (int j = 0; j < 4; j++) bb[j] = sm.g.Bs[kc][tx * 4 + j];
#pragma unroll
                for (int i = 0; i < 8; i++)
#pragma unroll
                    for (int j = 0; j < 4; j++)
                        acc[i][j] = fmaf(a[i], bb[j], acc[i][j]);
            }
            __syncthreads();
        }

        float* ob = out + (size_t)b * Nn * Cc;
        float4 bv4 = *(const float4*)(bias + o0 + tx * 4);
#pragma unroll
        for (int i = 0; i < 8; i++) {
            int n = n0 + ty * 8 + i;
            float4 r2;
            r2.x = fmaxf(acc[i][0] + bv4.x, 0.f);
            r2.y = fmaxf(acc[i][1] + bv4.y, 0.f);
            r2.z = fmaxf(acc[i][2] + bv4.z, 0.f);
            r2.w = fmaxf(acc[i][3] + bv4.w, 0.f);
            *(float4*)&ob[(size_t)n * Cc + o0 + tx * 4] = r2;
        }
    }
}

// ============================================================
// KNN merge — ranges ascending, strict-< insertion
// ============================================================
#define KNN_TPB 128

__global__ __launch_bounds__(KNN_TPB) void knn_merge_kernel()
{
    int b = blockIdx.y;
    int n = blockIdx.x * KNN_TPB + threadIdx.x;

    float bd[Kk];
    int   bi[Kk];
#pragma unroll
    for (int i = 0; i < Kk; i++) { bd[i] = 3.4e38f; bi[i] = 0; }

    size_t base = ((size_t)(b * Nn) + n) * NR * Kk;
    for (int e = 0; e < NR * Kk; e++) {
        float v = g_pd[base + e];
        int  ii = g_pi[base + e];
        if (v < bd[Kk - 1]) {
#pragma unroll
            for (int i = 0; i < Kk; i++) {
                if (v < bd[i]) {
                    float tv = bd[i]; int ti = bi[i];
                    bd[i] = v; bi[i] = ii;
                    v = tv; ii = ti;
                }
            }
        }
    }

    int* op = g_idx + ((size_t)(b * Nn) + n) * Kk;
#pragma unroll
    for (int i = 0; i < Kk; i++) op[i] = bi[i];
}

// ============================================================
// prep: pr (verbatim expressions) then packed {xk+pr, xv+pr}
// ============================================================
__global__ __launch_bounds__(256) void prep_kernel(
    const float* __restrict__ xyz,
    const float* __restrict__ Wp1, const float* __restrict__ bp1,
    const float* __restrict__ g1,  const float* __restrict__ b1,
    const float* __restrict__ Wp2, const float* __restrict__ bp2)
{
    int bm = blockIdx.x;
    int c = threadIdx.x;
    const float* p = xyz + (size_t)bm * 3;
    float p0 = p[0], p1v = p[1], p2 = p[2];
    float t[3];
#pragma unroll
    for (int o = 0; o < 3; o++) {
        float u = Wp1[o * 3 + 0] * p0 + Wp1[o * 3 + 1] * p1v
                + Wp1[o * 3 + 2] * p2 + bp1[o];
        u = u * (g1[o] * BN_INV) + b1[o];
        t[o] = fmaxf(u, 0.f);
    }
    float wp20 = Wp2[c * 3 + 0], wp21 = Wp2[c * 3 + 1], wp22 = Wp2[c * 3 + 2];
    float pr = fmaxf(wp20 * t[0] + wp21 * t[1] + wp22 * t[2] + bp2[c], 0.f);
    size_t base = (size_t)bm * Cc + c;
    g_kv2[base] = make_float2(g_k[base] + pr, g_v[base] + pr);
}

// ============================================================
// fused attention: packed gather; fp16 wv staging (smooth path,
// ~3e-5 output-relative); butterfly phase 3 with half the LDS;
// phase-4 w2t reuse; coalesced out
// ============================================================
__global__ __launch_bounds__(256, 4) void fused_kernel(
    const float* __restrict__ g0,  const float* __restrict__ b0,
    const float* __restrict__ Ww1, const float* __restrict__ bw1,
    const float* __restrict__ g2,  const float* __restrict__ b2,
    const float* __restrict__ Ww2, const float* __restrict__ bw2)
{
    int bx = blockIdx.x;
    int b = bx >> 13;
    int n = bx & (Nn - 1);
    int tid = threadIdx.x;
    int c = tid;
    int warp = tid >> 5;
    int lane = tid & 31;

    __shared__ __align__(16) __half wv_h[Kk][Cc];   // 8 KB
    __shared__ float w1_all[Kk][Dd];
    __shared__ float w_s[Kk][Dd];
    __shared__ float w2t_s[Dd * Dd];
    __shared__ int   idx_s[Kk];

    for (int i = tid; i < Dd * Dd; i += 256)
        w2t_s[i] = Ww2[(i & 31) * Dd + (i >> 5)];
    if (tid < Kk) idx_s[tid] = g_idx[((size_t)(b * Nn) + n) * Kk + tid];

    float xqc = g_q[((size_t)(b * Nn) + n) * Cc + c];
    float s0c = g0[c] * BN_INV, h0c = b0[c];
    float bw2r = bw2[lane];

    // phase-3 weights: warp handles d = 4*warp..4*warp+3;
    // lane covers c = 8*lane .. 8*lane+7 (one LDS.128 of fp16 per row)
    float w4[4][8];
#pragma unroll
    for (int i = 0; i < 4; i++) {
        const float* wr = Ww1 + (size_t)(4 * warp + i) * Cc + 8 * lane;
        float4 t0 = *(const float4*)(wr);
        float4 t1 = *(const float4*)(wr + 4);
        w4[i][0] = t0.x; w4[i][1] = t0.y; w4[i][2] = t0.z; w4[i][3] = t0.w;
        w4[i][4] = t1.x; w4[i][5] = t1.y; w4[i][6] = t1.z; w4[i][7] = t1.w;
    }
    int d_l = 4 * warp + (lane & 3);
    float bw1_l = bw1[d_l];
    float s2_l  = g2[d_l] * BN_INV;
    float h2_l  = b2[d_l];

    __syncthreads();

    // phase 2: single packed gather per neighbor; wv stored fp16
    float vreg[Kk];
#pragma unroll 4
    for (int kk = 0; kk < Kk; kk++) {
        int m = idx_s[kk];
        float2 kv = g_kv2[((size_t)(b * Nn) + m) * Cc + c];
        wv_h[kk][c] = __float2half_rn(fmaxf((kv.x - xqc) * s0c + h0c, 0.f));
        vreg[kk] = kv.y;
    }
    __syncthreads();

    // phase 3: w1 GEMV, 4 d per warp; one LDS.128 covers the whole
    // fp16 row (512B) per warp per kk
#pragma unroll 4
    for (int kk = 0; kk < Kk; kk++) {
        uint4 raw = *(const uint4*)(&wv_h[kk][8 * lane]);
        float2 f0 = __half22float2(*(const __half2*)&raw.x);
        float2 f1 = __half22float2(*(const __half2*)&raw.y);
        float2 f2 = __half22float2(*(const __half2*)&raw.z);
        float2 f3 = __half22float2(*(const __half2*)&raw.w);
        float a0 = 0.f, a1 = 0.f, a2 = 0.f, a3 = 0.f;
        a0 = fmaf(w4[0][0], f0.x, a0); a0 = fmaf(w4[0][1], f0.y, a0);
        a0 = fmaf(w4[0][2], f1.x, a0); a0 = fmaf(w4[0][3], f1.y, a0);
        a0 = fmaf(w4[0][4], f2.x, a0); a0 = fmaf(w4[0][5], f2.y, a0);
        a0 = fmaf(w4[0][6], f3.x, a0); a0 = fmaf(w4[0][7], f3.y, a0);
        a1 = fmaf(w4[1][0], f0.x, a1); a1 = fmaf(w4[1][1], f0.y, a1);
        a1 = fmaf(w4[1][2], f1.x, a1); a1 = fmaf(w4[1][3], f1.y, a1);
        a1 = fmaf(w4[1][4], f2.x, a1); a1 = fmaf(w4[1][5], f2.y, a1);
        a1 = fmaf(w4[1][6], f3.x, a1); a1 = fmaf(w4[1][7], f3.y, a1);
        a2 = fmaf(w4[2][0], f0.x, a2); a2 = fmaf(w4[2][1], f0.y, a2);
        a2 = fmaf(w4[2][2], f1.x, a2); a2 = fmaf(w4[2][3], f1.y, a2);
        a2 = fmaf(w4[2][4], f2.x, a2); a2 = fmaf(w4[2][5], f2.y, a2);
        a2 = fmaf(w4[2][6], f3.x, a2); a2 = fmaf(w4[2][7], f3.y, a2);
        a3 = fmaf(w4[3][0], f0.x, a3); a3 = fmaf(w4[3][1], f0.y, a3);
        a3 = fmaf(w4[3][2], f1.x, a3); a3 = fmaf(w4[3][3], f1.y, a3);
        a3 = fmaf(w4[3][4], f2.x, a3); a3 = fmaf(w4[3][5], f2.y, a3);
        a3 = fmaf(w4[3][6], f3.x, a3); a3 = fmaf(w4[3][7], f3.y, a3);
#pragma unroll
        for (int off = 16; off > 0; off >>= 1) {
            a0 += __shfl_xor_sync(0xffffffffu, a0, off);
            a1 += __shfl_xor_sync(0xffffffffu, a1, off);
            a2 += __shfl_xor_sync(0xffffffffu, a2, off);
            a3 += __shfl_xor_sync(0xffffffffu, a3, off);
        }
        if (lane < 4) {
            float t01 = (lane & 1) ? a1 : a0;
            float t23 = (lane & 1) ? a3 : a2;
            float part = (lane & 2) ? t23 : t01;
            float u = (part + bw1_l) * s2_l + h2_l;
            w1_all[kk][4 * warp + lane] = fmaxf(u, 0.f);
        }
    }
    __syncthreads();

    // phase 4: w2 — warp computes k in {2*warp, 2*warp+1}, e = lane;
    // w2t loaded once per dd feeds both k-chains
    {
        int k0 = 2 * warp, k1 = k0 + 1;
        float acc0 = bw2r, acc1 = bw2r;
#pragma unroll
        for (int dd = 0; dd < Dd; dd++) {
            float wv2 = w2t_s[dd * Dd + lane];
            acc0 = fmaf(wv2, w1_all[k0][dd], acc0);
            acc1 = fmaf(wv2, w1_all[k1][dd], acc1);
        }
        w_s[k0][lane] = fmaxf(acc0, 0.f);
        w_s[k1][lane] = fmaxf(acc1, 0.f);
    }
    __syncthreads();

    // softmax over K
    if (tid < Dd) {
        float mx = -3.4e38f;
#pragma unroll
        for (int kk = 0; kk < Kk; kk++) mx = fmaxf(mx, w_s[kk][tid]);
        float sum = 0.f;
#pragma unroll
        for (int kk = 0; kk < Kk; kk++) {
            float e = expf(w_s[kk][tid] - mx);
            w_s[kk][tid] = e;
            sum += e;
        }
        float rs = 1.0f / sum;
#pragma unroll
        for (int kk = 0; kk < Kk; kk++) w_s[kk][tid] *= rs;
    }
    __syncthreads();

    // weighted neighbor reduction; coalesced store to [b][n][c]
    float acc = 0.f;
    int dd = c & 31;
#pragma unroll
    for (int kk = 0; kk < Kk; kk++)
        acc = fmaf(vreg[kk], w_s[kk][dd], acc);
    g_tmp[((size_t)(b * Nn) + n) * Cc + c] = acc;
}

// ============================================================
// transpose: g_tmp [b][n][c] -> out [b][c][n]
// ============================================================
__global__ __launch_bounds__(256) void transpose_kernel(float* __restrict__ out)
{
    __shared__ float tile[32][33];
    int b  = blockIdx.z;
    int n0 = blockIdx.x * 32;
    int c0 = blockIdx.y * 32;
    int tx = threadIdx.x & 31;
    int ty = threadIdx.x >> 5;

#pragma unroll
    for (int i = 0; i < 4; i++) {
        int nn = ty + i * 8;
        tile[nn][tx] = g_tmp[((size_t)b * Nn + n0 + nn) * Cc + c0 + tx];
    }
    __syncthreads();
#pragma unroll
    for (int i = 0; i < 4; i++) {
        int cc = ty + i * 8;
        out[((size_t)b * Cc + c0 + cc) * Nn + n0 + tx] = tile[tx][cc];
    }
}

// ============================================================
// launch: super(2), merge(3), prep(4), fused(5), transpose(6)
// ============================================================
extern "C" void kernel_launch(void* const* d_in, const int* in_sizes, int n_in,
                              void* d_out, int out_size)
{
    const float* xyz  = (const float*)d_in[0];
    const float* feat = (const float*)d_in[1];
    const float* Wq = (const float*)d_in[2];   const float* bqp = (const float*)d_in[3];
    const float* Wk = (const float*)d_in[4];   const float* bkp = (const float*)d_in[5];
    const float* Wv = (const float*)d_in[6];   const float* bvp = (const float*)d_in[7];
    const float* Wp1 = (const float*)d_in[8];  const float* bp1 = (const float*)d_in[9];
    const float* g1  = (const float*)d_in[10]; const float* b1  = (const float*)d_in[11];
    const float* Wp2 = (const float*)d_in[12]; const float* bp2 = (const float*)d_in[13];
    const float* g0  = (const float*)d_in[14]; const float* b0  = (const float*)d_in[15];
    const float* Ww1 = (const float*)d_in[16]; const float* bw1 = (const float*)d_in[17];
    const float* g2  = (const float*)d_in[18]; const float* b2  = (const float*)d_in[19];
    const float* Ww2 = (const float*)d_in[20]; const float* bw2 = (const float*)d_in[21];
    float* out = (float*)d_out;

    super_kernel<<<KNN_NBLK + 3 * QKV_NBLK, 256>>>(feat, xyz,
                                                   Wq, bqp, Wk, bkp, Wv, bvp);

    dim3 mgrid(Nn / KNN_TPB, Bq);
    knn_merge_kernel<<<mgrid, KNN_TPB>>>();

    prep_kernel<<<Bq * Nn, 256>>>(xyz, Wp1, bp1, g1, b1, Wp2, bp2);

    fused_kernel<<<Bq * Nn, 256>>>(g0, b0, Ww1, bw1, g2, b2, Ww2, bw2);

    dim3 tgrid(Nn / 32, Cc / 32, Bq);
    transpose_kernel<<<tgrid, 256>>>(out);
}